// round 1
// baseline (speedup 1.0000x reference)
#include <cuda_runtime.h>
#include <mma.h>
#include <math.h>

using namespace nvcuda;

#define Bsz   1024
#define Wsz   6
#define Dsz   512
#define Vsz   50257
#define NSTEP 16

#define CUBIC_GAIN 0.032f   // CUBIC * GAIN = 0.008 * 4.0
#define LAM   0.1f
#define SIG   0.5f
#define EPSN  1e-8f
#define ASYM_STR 1.25f
#define LN_EPS 1e-5f

// scratch state buffers (device globals: no allocation allowed)
__device__ float g_S[Bsz * Wsz * Dsz];
__device__ float g_T[Bsz * Wsz * Dsz];

__device__ __forceinline__ float softplusf(float x) {
    return x > 0.f ? x + log1pf(expf(-x)) : log1pf(expf(x));
}

// ---------------------------------------------------------------------------
// Kernel 1: gather + LayerNorm.  grid = 6144 rows, block = 128 threads.
// ---------------------------------------------------------------------------
__global__ void gather_ln_kernel(const int* __restrict__ tokens,
                                 const float* __restrict__ embed) {
    int row = blockIdx.x;                 // 0 .. B*W-1
    int tok = tokens[row];
    const float4* src = reinterpret_cast<const float4*>(embed + (size_t)tok * Dsz);
    float4 v = src[threadIdx.x];          // 128 threads * 4 = 512

    float s  = v.x + v.y + v.z + v.w;
    float sq = v.x * v.x + v.y * v.y + v.z * v.z + v.w * v.w;

    __shared__ float sh_s[4], sh_q[4];
    #pragma unroll
    for (int o = 16; o > 0; o >>= 1) {
        s  += __shfl_down_sync(0xFFFFFFFFu, s, o);
        sq += __shfl_down_sync(0xFFFFFFFFu, sq, o);
    }
    int wid = threadIdx.x >> 5, lane = threadIdx.x & 31;
    if (lane == 0) { sh_s[wid] = s; sh_q[wid] = sq; }
    __syncthreads();
    float fs = sh_s[0] + sh_s[1] + sh_s[2] + sh_s[3];
    float fq = sh_q[0] + sh_q[1] + sh_q[2] + sh_q[3];
    float mu  = fs * (1.f / Dsz);
    float var = fq * (1.f / Dsz) - mu * mu;
    float rstd = rsqrtf(var + LN_EPS);

    float4 o;
    o.x = (v.x - mu) * rstd;
    o.y = (v.y - mu) * rstd;
    o.z = (v.z - mu) * rstd;
    o.w = (v.w - mu) * rstd;
    reinterpret_cast<float4*>(g_S + (size_t)row * Dsz)[threadIdx.x] = o;
}

// ---------------------------------------------------------------------------
// TF32 wmma GEMM:  C[m,n] = sum_k A[m,k] * Bmat[n,k]
//   A    = g_S (row-major, ld = K)
//   Bmat = row-major [N,K]  (i.e. col-major K x N with ld = K)
//   C    = out_ptr if non-null else g_T
// BM=128, BN=128, BK=32, 256 threads (8 warps, 2x4), per warp 64x32 -> 4x2 frags.
// M, K must be multiples of 128/32; N handled with guards.
// ---------------------------------------------------------------------------
#define GBM 128
#define GBN 128
#define GBK 32
#define GPAD 4

__global__ __launch_bounds__(256)
void gemm_tn_tf32(const float* __restrict__ Bmat, float* __restrict__ out_ptr,
                  int M, int N, int K) {
    const float* __restrict__ A = g_S;
    float* __restrict__ C = out_ptr ? out_ptr : g_T;

    __shared__ float As[GBM][GBK + GPAD];
    __shared__ float Bs[GBN][GBK + GPAD];
    __shared__ float Cbuf[8][256];

    int m0 = blockIdx.x * GBM;
    int n0 = blockIdx.y * GBN;
    int tid = threadIdx.x;
    int warp = tid >> 5, lane = tid & 31;
    int warp_m = warp >> 2;   // 0..1
    int warp_n = warp & 3;    // 0..3

    wmma::fragment<wmma::accumulator, 16, 16, 8, float> acc[4][2];
    #pragma unroll
    for (int mi = 0; mi < 4; mi++)
        #pragma unroll
        for (int ni = 0; ni < 2; ni++)
            wmma::fill_fragment(acc[mi][ni], 0.0f);

    for (int k0 = 0; k0 < K; k0 += GBK) {
        // load A tile: 128 rows x 32 cols = 1024 float4-chunks/4 -> 4 per thread
        #pragma unroll
        for (int t = 0; t < 4; t++) {
            int idx = tid + t * 256;        // 0..1023
            int r = idx >> 3, c4 = idx & 7;
            float4 v = *reinterpret_cast<const float4*>(
                A + (size_t)(m0 + r) * K + k0 + c4 * 4);
            v.x = wmma::__float_to_tf32(v.x);
            v.y = wmma::__float_to_tf32(v.y);
            v.z = wmma::__float_to_tf32(v.z);
            v.w = wmma::__float_to_tf32(v.w);
            *reinterpret_cast<float4*>(&As[r][c4 * 4]) = v;
        }
        // load B tile (guard n < N, zero-fill tail)
        #pragma unroll
        for (int t = 0; t < 4; t++) {
            int idx = tid + t * 256;
            int r = idx >> 3, c4 = idx & 7;
            int n = n0 + r;
            float4 v;
            if (n < N) {
                v = *reinterpret_cast<const float4*>(
                    Bmat + (size_t)n * K + k0 + c4 * 4);
                v.x = wmma::__float_to_tf32(v.x);
                v.y = wmma::__float_to_tf32(v.y);
                v.z = wmma::__float_to_tf32(v.z);
                v.w = wmma::__float_to_tf32(v.w);
            } else {
                v = make_float4(0.f, 0.f, 0.f, 0.f);
            }
            *reinterpret_cast<float4*>(&Bs[r][c4 * 4]) = v;
        }
        __syncthreads();

        #pragma unroll
        for (int ks = 0; ks < GBK; ks += 8) {
            wmma::fragment<wmma::matrix_a, 16, 16, 8, wmma::precision::tf32,
                           wmma::row_major> af[4];
            wmma::fragment<wmma::matrix_b, 16, 16, 8, wmma::precision::tf32,
                           wmma::col_major> bf[2];
            #pragma unroll
            for (int mi = 0; mi < 4; mi++)
                wmma::load_matrix_sync(af[mi], &As[warp_m * 64 + mi * 16][ks], GBK + GPAD);
            #pragma unroll
            for (int ni = 0; ni < 2; ni++)
                wmma::load_matrix_sync(bf[ni], &Bs[warp_n * 32 + ni * 16][ks], GBK + GPAD);
            #pragma unroll
            for (int mi = 0; mi < 4; mi++)
                #pragma unroll
                for (int ni = 0; ni < 2; ni++)
                    wmma::mma_sync(acc[mi][ni], af[mi], bf[ni], acc[mi][ni]);
        }
        __syncthreads();
    }

    // store via per-warp smem staging (bounded on N)
    float* wbuf = Cbuf[warp];
    #pragma unroll
    for (int mi = 0; mi < 4; mi++) {
        #pragma unroll
        for (int ni = 0; ni < 2; ni++) {
            wmma::store_matrix_sync(wbuf, acc[mi][ni], 16, wmma::mem_row_major);
            __syncwarp();
            int mrow0 = m0 + warp_m * 64 + mi * 16;
            int ncol0 = n0 + warp_n * 32 + ni * 16;
            #pragma unroll
            for (int e = lane; e < 256; e += 32) {
                int rr = e >> 4, cc = e & 15;
                int n = ncol0 + cc;
                if (n < N)
                    C[(size_t)(mrow0 + rr) * N + n] = wbuf[e];
            }
            __syncwarp();
        }
    }
}

// ---------------------------------------------------------------------------
// Kernel 3: fused coupling + nonlinearity + euler step + normalize.
// grid = 1024 (one block per batch element), block = 512 (one thread per d).
// ---------------------------------------------------------------------------
__device__ __forceinline__ void block_reduce6(float v[Wsz], float red[Wsz][16],
                                              int wid, int lane) {
    #pragma unroll
    for (int i = 0; i < Wsz; i++) {
        float x = v[i];
        #pragma unroll
        for (int o = 16; o > 0; o >>= 1)
            x += __shfl_down_sync(0xFFFFFFFFu, x, o);
        if (lane == 0) red[i][wid] = x;
    }
    __syncthreads();
    #pragma unroll
    for (int i = 0; i < Wsz; i++) {
        float t = 0.f;
        #pragma unroll
        for (int w = 0; w < 16; w++) t += red[i][w];
        v[i] = t;
    }
    __syncthreads();
}

__global__ __launch_bounds__(512)
void update_kernel(const float* __restrict__ beta_p,
                   const float* __restrict__ gamma_raw,
                   const float* __restrict__ scale_raw,
                   const float* __restrict__ dt_raw,
                   const float* __restrict__ asym_p) {
    int b = blockIdx.x;
    int d = threadIdx.x;
    int wid = d >> 5, lane = d & 31;

    __shared__ float Wsh[Wsz][Wsz];
    __shared__ float wsumsh[Wsz];
    __shared__ float red[Wsz][16];

    float gamma = softplusf(*gamma_raw);
    float scale = softplusf(*scale_raw);
    float dt    = softplusf(*dt_raw);
    float beta  = *beta_p;
    float ta    = tanhf(*asym_p);
    float coeff = beta * SIG * scale;   // folded signal coefficient

    if (d < Wsz * Wsz) {
        int i = d / Wsz, j = d % Wsz;
        float w = 0.f;
        if (i != j) {
            float ji = (float)(j - i);
            float sgn = (ji > 0.f) ? 1.f : -1.f;
            float af = fmaxf(1.f + ASYM_STR * ta * sgn, 0.2f);
            w = expf(-gamma * fabsf(ji)) * af * coeff;
        }
        Wsh[i][j] = w;
    }
    __syncthreads();
    if (d < Wsz) {
        float ws = 0.f;
        #pragma unroll
        for (int j = 0; j < Wsz; j++) ws += Wsh[d][j];
        wsumsh[d] = ws;
    }
    __syncthreads();

    size_t base = (size_t)b * Wsz * Dsz + d;
    float s_loc[Wsz], t_loc[Wsz];
    #pragma unroll
    for (int i = 0; i < Wsz; i++) {
        s_loc[i] = g_S[base + i * Dsz];
        t_loc[i] = g_T[base + i * Dsz];
    }

    // per-row means over D
    float mu[Wsz];
    #pragma unroll
    for (int i = 0; i < Wsz; i++) mu[i] = s_loc[i];
    block_reduce6(mu, red, wid, lane);
    #pragma unroll
    for (int i = 0; i < Wsz; i++) mu[i] *= (1.f / Dsz);

    float sn[Wsz], sq[Wsz];
    #pragma unroll
    for (int i = 0; i < Wsz; i++) {
        float sig = -wsumsh[i] * s_loc[i];
        #pragma unroll
        for (int j = 0; j < Wsz; j++)
            sig = fmaf(Wsh[i][j], s_loc[j], sig);
        float c = s_loc[i] - mu[i];
        float drift = t_loc[i] + CUBIC_GAIN * tanhf(c) + sig - LAM * s_loc[i];
        float v = fmaf(dt, drift, s_loc[i]);
        if (!isfinite(v)) v = 0.f;        // nan_to_num(nan/inf -> 0)
        sn[i] = v;
        sq[i] = v * v;
    }

    block_reduce6(sq, red, wid, lane);

    #pragma unroll
    for (int i = 0; i < Wsz; i++) {
        float nrm = sqrtf(sq[i]);
        float o = sn[i] / (nrm + EPSN);
        o = fminf(fmaxf(o, -10.f), 10.f);
        g_S[base + i * Dsz] = o;
    }
}

// ---------------------------------------------------------------------------
// launch
// ---------------------------------------------------------------------------
extern "C" void kernel_launch(void* const* d_in, const int* in_sizes, int n_in,
                              void* d_out, int out_size) {
    const int*   tokens    = (const int*)d_in[0];
    const float* embed     = (const float*)d_in[1];
    const float* diffusion = (const float*)d_in[2];
    const float* readout   = (const float*)d_in[3];
    const float* beta      = (const float*)d_in[4];
    const float* g_raw     = (const float*)d_in[5];
    const float* s_raw     = (const float*)d_in[6];
    const float* dtraw     = (const float*)d_in[7];
    const float* asym      = (const float*)d_in[8];
    float* out = (float*)d_out;

    gather_ln_kernel<<<Bsz * Wsz, 128>>>(tokens, embed);

    for (int s = 0; s < NSTEP; s++) {
        // g_T = g_S @ diffusion^T   (M=6144, N=512, K=512)
        gemm_tn_tf32<<<dim3((Bsz * Wsz) / GBM, Dsz / GBN), 256>>>(
            diffusion, nullptr, Bsz * Wsz, Dsz, Dsz);
        update_kernel<<<Bsz, Dsz>>>(beta, g_raw, s_raw, dtraw, asym);
    }

    // logits = S.reshape(B, W*D) @ readout^T   (M=1024, N=50257, K=3072)
    gemm_tn_tf32<<<dim3(Bsz / GBM, (Vsz + GBN - 1) / GBN), 256>>>(
        readout, out, Bsz, Vsz, Wsz * Dsz);
}

// round 4
// speedup vs baseline: 1.0071x; 1.0071x over previous
#include <cuda_runtime.h>
#include <mma.h>
#include <math.h>
#include <cstdint>

using namespace nvcuda;

#define Bsz   1024
#define Wsz   6
#define Dsz   512
#define Vsz   50257
#define NSTEP 16

#define CUBIC_GAIN 0.032f   // CUBIC * GAIN = 0.008 * 4.0
#define LAM   0.1f
#define SIG   0.5f
#define EPSN  1e-8f
#define ASYM_STR 1.25f
#define LN_EPS 1e-5f

// scratch state buffers (device globals: no allocation allowed)
__device__ float g_S[Bsz * Wsz * Dsz];
__device__ float g_T[Bsz * Wsz * Dsz];

__device__ __forceinline__ float softplusf(float x) {
    return x > 0.f ? x + log1pf(expf(-x)) : log1pf(expf(x));
}

// ---------------------------------------------------------------------------
// Kernel 1: gather + LayerNorm.  grid = 6144 rows, block = 128 threads.
// ---------------------------------------------------------------------------
__global__ void gather_ln_kernel(const int* __restrict__ tokens,
                                 const float* __restrict__ embed) {
    int row = blockIdx.x;                 // 0 .. B*W-1
    int tok = tokens[row];
    const float4* src = reinterpret_cast<const float4*>(embed + (size_t)tok * Dsz);
    float4 v = src[threadIdx.x];          // 128 threads * 4 = 512

    float s  = v.x + v.y + v.z + v.w;
    float sq = v.x * v.x + v.y * v.y + v.z * v.z + v.w * v.w;

    __shared__ float sh_s[4], sh_q[4];
    #pragma unroll
    for (int o = 16; o > 0; o >>= 1) {
        s  += __shfl_down_sync(0xFFFFFFFFu, s, o);
        sq += __shfl_down_sync(0xFFFFFFFFu, sq, o);
    }
    int wid = threadIdx.x >> 5, lane = threadIdx.x & 31;
    if (lane == 0) { sh_s[wid] = s; sh_q[wid] = sq; }
    __syncthreads();
    float fs = sh_s[0] + sh_s[1] + sh_s[2] + sh_s[3];
    float fq = sh_q[0] + sh_q[1] + sh_q[2] + sh_q[3];
    float mu  = fs * (1.f / Dsz);
    float var = fq * (1.f / Dsz) - mu * mu;
    float rstd = rsqrtf(var + LN_EPS);

    float4 o;
    o.x = (v.x - mu) * rstd;
    o.y = (v.y - mu) * rstd;
    o.z = (v.z - mu) * rstd;
    o.w = (v.w - mu) * rstd;
    reinterpret_cast<float4*>(g_S + (size_t)row * Dsz)[threadIdx.x] = o;
}

// ---------------------------------------------------------------------------
// TF32 wmma GEMM v2, cp.async double-buffered:
//   C[m,n] = sum_k A[m,k] * Bmat[n,k]
//   A = g_S (row-major, ld=K), Bmat row-major [N,K], C = out_ptr ?: g_T
// BM=128, BN=128, BK=32, 2 stages, 256 threads (8 warps 2x4, warp tile 64x32).
// M, K multiples of 128/32.
// Direct fragment store only when N % 4 == 0 AND tile is interior
// (store_matrix_sync needs 16B-multiple leading dimension); otherwise
// stage through smem with scalar guarded stores.
// ---------------------------------------------------------------------------
#define GBM 128
#define GBN 128
#define GBK 32
#define GPAD 4
#define GLDS (GBK + GPAD)            // 36 floats per smem row
#define GSTAGES 2
#define GEMM_SMEM_BYTES (GSTAGES * (GBM + GBN) * GLDS * 4)

__device__ __forceinline__ void cp_async16(float* smem_dst, const float* gmem_src,
                                           bool valid) {
    unsigned int saddr = (unsigned int)__cvta_generic_to_shared(smem_dst);
    int sz = valid ? 16 : 0;
    asm volatile("cp.async.ca.shared.global [%0], [%1], 16, %2;\n"
                 :: "r"(saddr), "l"(gmem_src), "r"(sz));
}

__global__ __launch_bounds__(256, 2)
void gemm_tn_v2(const float* __restrict__ Bmat, float* __restrict__ out_ptr,
                int M, int N, int K) {
    extern __shared__ float sm[];
    float* As = sm;                         // [GSTAGES][GBM][GLDS]
    float* Bs = sm + GSTAGES * GBM * GLDS;  // [GSTAGES][GBN][GLDS]

    const float* __restrict__ A = g_S;
    float* __restrict__ C = out_ptr ? out_ptr : g_T;

    const int m0 = blockIdx.x * GBM;
    const int n0 = blockIdx.y * GBN;
    const int tid = threadIdx.x;
    const int warp = tid >> 5, lane = tid & 31;
    const int wm = warp >> 2;            // 0..1
    const int wn = warp & 3;             // 0..3
    const int r_ld = tid >> 3;           // 0..31
    const int c_ld = (tid & 7) * 4;      // 0,4,..,28

    wmma::fragment<wmma::accumulator, 16, 16, 8, float> acc[4][2];
    #pragma unroll
    for (int mi = 0; mi < 4; mi++)
        #pragma unroll
        for (int ni = 0; ni < 2; ni++)
            wmma::fill_fragment(acc[mi][ni], 0.0f);

    const int niter = K / GBK;

    auto load_stage = [&](int st, int k0) {
        float* as = As + st * GBM * GLDS;
        float* bs = Bs + st * GBN * GLDS;
        #pragma unroll
        for (int t = 0; t < 4; t++) {
            int r = r_ld + t * 32;
            cp_async16(as + r * GLDS + c_ld,
                       A + (size_t)(m0 + r) * K + k0 + c_ld, true);
        }
        #pragma unroll
        for (int t = 0; t < 4; t++) {
            int r = r_ld + t * 32;
            int n = n0 + r;
            bool v = (n < N);
            cp_async16(bs + r * GLDS + c_ld,
                       Bmat + (size_t)(v ? n : 0) * K + k0 + c_ld, v);
        }
        asm volatile("cp.async.commit_group;\n" ::: "memory");
    };

    load_stage(0, 0);

    for (int i = 0; i < niter; i++) {
        if (i + 1 < niter) {
            load_stage((i + 1) & 1, (i + 1) * GBK);
            asm volatile("cp.async.wait_group 1;\n" ::: "memory");
        } else {
            asm volatile("cp.async.wait_group 0;\n" ::: "memory");
        }
        __syncthreads();

        const int st = i & 1;
        const float* as = As + st * GBM * GLDS;
        const float* bs = Bs + st * GBN * GLDS;

        #pragma unroll
        for (int ks = 0; ks < GBK; ks += 8) {
            wmma::fragment<wmma::matrix_a, 16, 16, 8, wmma::precision::tf32,
                           wmma::row_major> af[4];
            wmma::fragment<wmma::matrix_b, 16, 16, 8, wmma::precision::tf32,
                           wmma::col_major> bf[2];
            #pragma unroll
            for (int mi = 0; mi < 4; mi++) {
                wmma::load_matrix_sync(af[mi],
                    as + (size_t)(wm * 64 + mi * 16) * GLDS + ks, GLDS);
                #pragma unroll
                for (int e = 0; e < af[mi].num_elements; e++)
                    af[mi].x[e] = wmma::__float_to_tf32(af[mi].x[e]);
            }
            #pragma unroll
            for (int ni = 0; ni < 2; ni++) {
                wmma::load_matrix_sync(bf[ni],
                    bs + (size_t)(wn * 32 + ni * 16) * GLDS + ks, GLDS);
                #pragma unroll
                for (int e = 0; e < bf[ni].num_elements; e++)
                    bf[ni].x[e] = wmma::__float_to_tf32(bf[ni].x[e]);
            }
            #pragma unroll
            for (int mi = 0; mi < 4; mi++)
                #pragma unroll
                for (int ni = 0; ni < 2; ni++)
                    wmma::mma_sync(acc[mi][ni], af[mi], bf[ni], acc[mi][ni]);
        }
        __syncthreads();
    }

    // Direct fragment store needs ld (=N) to be a multiple of 4 floats (16B)
    // AND a fully interior tile. Final GEMM (N=50257, odd) always stages.
    if (((N & 3) == 0) && (n0 + GBN <= N)) {
        #pragma unroll
        for (int mi = 0; mi < 4; mi++)
            #pragma unroll
            for (int ni = 0; ni < 2; ni++) {
                size_t off = (size_t)(m0 + wm * 64 + mi * 16) * N
                           + (n0 + wn * 32 + ni * 16);
                wmma::store_matrix_sync(C + off, acc[mi][ni], N,
                                        wmma::mem_row_major);
            }
    } else {
        // stage through smem with column guards (scalar stores, any N)
        float* wbuf = sm + warp * 256;
        #pragma unroll
        for (int mi = 0; mi < 4; mi++) {
            #pragma unroll
            for (int ni = 0; ni < 2; ni++) {
                wmma::store_matrix_sync(wbuf, acc[mi][ni], 16,
                                        wmma::mem_row_major);
                __syncwarp();
                int mrow0 = m0 + wm * 64 + mi * 16;
                int ncol0 = n0 + wn * 32 + ni * 16;
                #pragma unroll
                for (int e = lane; e < 256; e += 32) {
                    int rr = e >> 4, cc = e & 15;
                    int n = ncol0 + cc;
                    if (n < N)
                        C[(size_t)(mrow0 + rr) * N + n] = wbuf[e];
                }
                __syncwarp();
            }
        }
    }
}

// ---------------------------------------------------------------------------
// Kernel 3: fused coupling + nonlinearity + euler step + normalize.
// grid = 1024 (one block per batch element), block = 512 (one thread per d).
// ---------------------------------------------------------------------------
__device__ __forceinline__ void block_reduce6(float v[Wsz], float red[Wsz][16],
                                              int wid, int lane) {
    #pragma unroll
    for (int i = 0; i < Wsz; i++) {
        float x = v[i];
        #pragma unroll
        for (int o = 16; o > 0; o >>= 1)
            x += __shfl_down_sync(0xFFFFFFFFu, x, o);
        if (lane == 0) red[i][wid] = x;
    }
    __syncthreads();
    #pragma unroll
    for (int i = 0; i < Wsz; i++) {
        float t = 0.f;
        #pragma unroll
        for (int w = 0; w < 16; w++) t += red[i][w];
        v[i] = t;
    }
    __syncthreads();
}

__global__ __launch_bounds__(512)
void update_kernel(const float* __restrict__ beta_p,
                   const float* __restrict__ gamma_raw,
                   const float* __restrict__ scale_raw,
                   const float* __restrict__ dt_raw,
                   const float* __restrict__ asym_p) {
    int b = blockIdx.x;
    int d = threadIdx.x;
    int wid = d >> 5, lane = d & 31;

    __shared__ float Wsh[Wsz][Wsz];
    __shared__ float wsumsh[Wsz];
    __shared__ float red[Wsz][16];

    float gamma = softplusf(*gamma_raw);
    float scale = softplusf(*scale_raw);
    float dt    = softplusf(*dt_raw);
    float beta  = *beta_p;
    float ta    = tanhf(*asym_p);
    float coeff = beta * SIG * scale;   // folded signal coefficient

    if (d < Wsz * Wsz) {
        int i = d / Wsz, j = d % Wsz;
        float w = 0.f;
        if (i != j) {
            float ji = (float)(j - i);
            float sgn = (ji > 0.f) ? 1.f : -1.f;
            float af = fmaxf(1.f + ASYM_STR * ta * sgn, 0.2f);
            w = expf(-gamma * fabsf(ji)) * af * coeff;
        }
        Wsh[i][j] = w;
    }
    __syncthreads();
    if (d < Wsz) {
        float ws = 0.f;
        #pragma unroll
        for (int j = 0; j < Wsz; j++) ws += Wsh[d][j];
        wsumsh[d] = ws;
    }
    __syncthreads();

    size_t base = (size_t)b * Wsz * Dsz + d;
    float s_loc[Wsz], t_loc[Wsz];
    #pragma unroll
    for (int i = 0; i < Wsz; i++) {
        s_loc[i] = g_S[base + i * Dsz];
        t_loc[i] = g_T[base + i * Dsz];
    }

    // per-row means over D
    float mu[Wsz];
    #pragma unroll
    for (int i = 0; i < Wsz; i++) mu[i] = s_loc[i];
    block_reduce6(mu, red, wid, lane);
    #pragma unroll
    for (int i = 0; i < Wsz; i++) mu[i] *= (1.f / Dsz);

    float sn[Wsz], sq[Wsz];
    #pragma unroll
    for (int i = 0; i < Wsz; i++) {
        float sig = -wsumsh[i] * s_loc[i];
        #pragma unroll
        for (int j = 0; j < Wsz; j++)
            sig = fmaf(Wsh[i][j], s_loc[j], sig);
        float c = s_loc[i] - mu[i];
        float drift = t_loc[i] + CUBIC_GAIN * tanhf(c) + sig - LAM * s_loc[i];
        float v = fmaf(dt, drift, s_loc[i]);
        if (!isfinite(v)) v = 0.f;        // nan_to_num(nan/inf -> 0)
        sn[i] = v;
        sq[i] = v * v;
    }

    block_reduce6(sq, red, wid, lane);

    #pragma unroll
    for (int i = 0; i < Wsz; i++) {
        float nrm = sqrtf(sq[i]);
        float o = sn[i] / (nrm + EPSN);
        o = fminf(fmaxf(o, -10.f), 10.f);
        g_S[base + i * Dsz] = o;
    }
}

// ---------------------------------------------------------------------------
// launch
// ---------------------------------------------------------------------------
extern "C" void kernel_launch(void* const* d_in, const int* in_sizes, int n_in,
                              void* d_out, int out_size) {
    const int*   tokens    = (const int*)d_in[0];
    const float* embed     = (const float*)d_in[1];
    const float* diffusion = (const float*)d_in[2];
    const float* readout   = (const float*)d_in[3];
    const float* beta      = (const float*)d_in[4];
    const float* g_raw     = (const float*)d_in[5];
    const float* s_raw     = (const float*)d_in[6];
    const float* dtraw     = (const float*)d_in[7];
    const float* asym      = (const float*)d_in[8];
    float* out = (float*)d_out;

    cudaFuncSetAttribute(gemm_tn_v2,
                         cudaFuncAttributeMaxDynamicSharedMemorySize,
                         GEMM_SMEM_BYTES);

    gather_ln_kernel<<<Bsz * Wsz, 128>>>(tokens, embed);

    for (int s = 0; s < NSTEP; s++) {
        // g_T = g_S @ diffusion^T   (M=6144, N=512, K=512)
        gemm_tn_v2<<<dim3((Bsz * Wsz) / GBM, Dsz / GBN), 256, GEMM_SMEM_BYTES>>>(
            diffusion, nullptr, Bsz * Wsz, Dsz, Dsz);
        update_kernel<<<Bsz, Dsz>>>(beta, g_raw, s_raw, dtraw, asym);
    }

    // logits = S.reshape(B, W*D) @ readout^T   (M=1024, N=50257, K=3072)
    gemm_tn_v2<<<dim3(Bsz / GBM, (Vsz + GBN - 1) / GBN), 256, GEMM_SMEM_BYTES>>>(
        readout, out, Bsz, Vsz, Wsz * Dsz);
}